// round 6
// baseline (speedup 1.0000x reference)
#include <cuda_runtime.h>
#include <cuda_bf16.h>
#include <math.h>

#define N_NODES  1000000
#define N_EDGES  16000000
#define N_GRAPHS 1024

// ---------------- scratch (device globals: allocation-free) ----------------
__device__ float4 g_bufA[2000000];   // 8M floats: x1 (1M x 8), reused as agg2 (1M x 4)
__device__ float4 g_bufB[2000000];   // 8M floats: agg1 (1M x 8)
__device__ float4 g_bufC[1000000];   // 4M floats: x2 (1M x 4)
__device__ int    g_deg_out[N_NODES];
__device__ int    g_deg_in[N_NODES];
__device__ float  g_gsum[N_GRAPHS * 4];
__device__ float  g_gcnt[N_GRAPHS];

// vectorized global reduction (sm_90+): 4x fewer atomic ops
__device__ __forceinline__ void red_add_v4(float* p, float4 v) {
    asm volatile("red.global.add.v4.f32 [%0], {%1,%2,%3,%4};"
                 :: "l"(p), "f"(v.x), "f"(v.y), "f"(v.z), "f"(v.w) : "memory");
}

// ---------------- kernels ----------------

// zero agg1 (8M floats), degrees, graph accumulators
__global__ void k_zero_all() {
    int i = blockIdx.x * blockDim.x + threadIdx.x;
    float4 z = make_float4(0.f, 0.f, 0.f, 0.f);
    if (i < 2000000) g_bufB[i] = z;
    if (i < N_NODES / 2) { ((int2*)g_deg_out)[i] = make_int2(0, 0);
                           ((int2*)g_deg_in)[i]  = make_int2(0, 0); }
    if (i < N_GRAPHS) { ((float4*)g_gsum)[i] = z; g_gcnt[i] = 0.f; }
}

// zero agg2 region (first 4M floats of bufA)
__global__ void k_zero_agg2() {
    int i = blockIdx.x * blockDim.x + threadIdx.x;
    if (i < 1000000) g_bufA[i] = make_float4(0.f, 0.f, 0.f, 0.f);
}

// degree computation: 4 edges per thread
__global__ void k_degrees(const int* __restrict__ src, const int* __restrict__ dst) {
    int i = blockIdx.x * blockDim.x + threadIdx.x;
    if (i >= N_EDGES / 4) return;
    int4 s = ((const int4*)src)[i];
    int4 d = ((const int4*)dst)[i];
    atomicAdd(&g_deg_out[s.x], 1); atomicAdd(&g_deg_out[s.y], 1);
    atomicAdd(&g_deg_out[s.z], 1); atomicAdd(&g_deg_out[s.w], 1);
    atomicAdd(&g_deg_in[d.x], 1);  atomicAdd(&g_deg_in[d.y], 1);
    atomicAdd(&g_deg_in[d.z], 1);  atomicAdd(&g_deg_in[d.w], 1);
}

// x1 = (features * out_norm) @ W1   -> bufA (1M x 8)
__global__ void k_proj1(const float* __restrict__ feat, const float* __restrict__ W1) {
    __shared__ float sW[80];
    if (threadIdx.x < 80) sW[threadIdx.x] = W1[threadIdx.x];
    __syncthreads();
    int n = blockIdx.x * blockDim.x + threadIdx.x;
    if (n >= N_NODES) return;
    float onorm = rsqrtf(fmaxf((float)g_deg_out[n], 1.f));
    const float2* fp = (const float2*)(feat + (size_t)n * 10);
    float f[10];
#pragma unroll
    for (int i = 0; i < 5; i++) { float2 v = fp[i]; f[2*i] = v.x * onorm; f[2*i+1] = v.y * onorm; }
    float o[8];
#pragma unroll
    for (int j = 0; j < 8; j++) o[j] = 0.f;
#pragma unroll
    for (int i = 0; i < 10; i++)
#pragma unroll
        for (int j = 0; j < 8; j++) o[j] += f[i] * sW[i * 8 + j];
    g_bufA[(size_t)n * 2]     = make_float4(o[0], o[1], o[2], o[3]);
    g_bufA[(size_t)n * 2 + 1] = make_float4(o[4], o[5], o[6], o[7]);
}

// agg1[dst] += x1[src]   (8 floats per edge = 2 vector REDs)
__global__ void k_scatter1(const int* __restrict__ src, const int* __restrict__ dst) {
    int e = blockIdx.x * blockDim.x + threadIdx.x;
    if (e >= N_EDGES) return;
    int s = __ldg(src + e);
    int d = __ldg(dst + e);
    float4 x0 = __ldg(&g_bufA[(size_t)s * 2]);
    float4 x1 = __ldg(&g_bufA[(size_t)s * 2 + 1]);
    float* dp = (float*)&g_bufB[(size_t)d * 2];
    red_add_v4(dp,     x0);
    red_add_v4(dp + 4, x1);
}

// h1 = relu(agg1 * in_norm + b1); x2 = (h1 * out_norm) @ W2 -> bufC (1M x 4)
__global__ void k_h1_proj2(const float* __restrict__ W2, const float* __restrict__ b1) {
    __shared__ float sW[32], sb[8];
    if (threadIdx.x < 32) sW[threadIdx.x] = W2[threadIdx.x];
    if (threadIdx.x < 8)  sb[threadIdx.x] = b1[threadIdx.x];
    __syncthreads();
    int n = blockIdx.x * blockDim.x + threadIdx.x;
    if (n >= N_NODES) return;
    float innorm = rsqrtf(fmaxf((float)g_deg_in[n], 1.f));
    float onorm  = rsqrtf(fmaxf((float)g_deg_out[n], 1.f));
    float4 a0 = g_bufB[(size_t)n * 2];
    float4 a1 = g_bufB[(size_t)n * 2 + 1];
    float h[8] = { a0.x, a0.y, a0.z, a0.w, a1.x, a1.y, a1.z, a1.w };
#pragma unroll
    for (int j = 0; j < 8; j++) h[j] = fmaxf(h[j] * innorm + sb[j], 0.f);
    float o[4] = {0.f, 0.f, 0.f, 0.f};
#pragma unroll
    for (int j = 0; j < 8; j++)
#pragma unroll
        for (int k = 0; k < 4; k++) o[k] += h[j] * sW[j * 4 + k];
    g_bufC[n] = make_float4(o[0] * onorm, o[1] * onorm, o[2] * onorm, o[3] * onorm);
}

// agg2[dst] += x2[src]   (4 floats per edge = 1 vector RED)
__global__ void k_scatter2(const int* __restrict__ src, const int* __restrict__ dst) {
    int e = blockIdx.x * blockDim.x + threadIdx.x;
    if (e >= N_EDGES) return;
    int s = __ldg(src + e);
    int d = __ldg(dst + e);
    float4 x = __ldg(&g_bufC[s]);
    red_add_v4((float*)&g_bufA[d], x);
}

// h2 = relu(agg2 * in_norm + b2); segment-sum into graphs (warp-aggregated;
// graph_ids is sorted so warps are almost always uniform in gid)
__global__ void k_graph_reduce(const int* __restrict__ graph_ids, const float* __restrict__ b2) {
    int n = blockIdx.x * blockDim.x + threadIdx.x;
    bool valid = (n < N_NODES);
    int nn = valid ? n : (N_NODES - 1);
    float4 a = valid ? g_bufA[nn] : make_float4(0.f, 0.f, 0.f, 0.f);
    float innorm = rsqrtf(fmaxf((float)g_deg_in[nn], 1.f));
    float h[4];
    h[0] = valid ? fmaxf(a.x * innorm + __ldg(b2 + 0), 0.f) : 0.f;
    h[1] = valid ? fmaxf(a.y * innorm + __ldg(b2 + 1), 0.f) : 0.f;
    h[2] = valid ? fmaxf(a.z * innorm + __ldg(b2 + 2), 0.f) : 0.f;
    h[3] = valid ? fmaxf(a.w * innorm + __ldg(b2 + 3), 0.f) : 0.f;
    float cnt = valid ? 1.f : 0.f;
    int gid = __ldg(graph_ids + nn);

    unsigned full = 0xFFFFFFFFu;
    int g0 = __shfl_sync(full, gid, 0);
    bool uniform = __all_sync(full, gid == g0);
    int lane = threadIdx.x & 31;
    if (uniform) {
#pragma unroll
        for (int off = 16; off > 0; off >>= 1) {
#pragma unroll
            for (int k = 0; k < 4; k++) h[k] += __shfl_down_sync(full, h[k], off);
            cnt += __shfl_down_sync(full, cnt, off);
        }
        if (lane == 0) {
#pragma unroll
            for (int k = 0; k < 4; k++) atomicAdd(&g_gsum[g0 * 4 + k], h[k]);
            atomicAdd(&g_gcnt[g0], cnt);
        }
    } else if (valid) {
#pragma unroll
        for (int k = 0; k < 4; k++) atomicAdd(&g_gsum[gid * 4 + k], h[k]);
        atomicAdd(&g_gcnt[gid], 1.f);
    }
}

// out[g] = sigmoid(mean @ Wo + bo)
__global__ void k_final(const float* __restrict__ Wo, const float* __restrict__ bo,
                        float* __restrict__ out) {
    int g = blockIdx.x * blockDim.x + threadIdx.x;
    if (g >= N_GRAPHS) return;
    float c = fmaxf(g_gcnt[g], 1.f);
    float z = __ldg(bo);
#pragma unroll
    for (int k = 0; k < 4; k++) z += (g_gsum[g * 4 + k] / c) * __ldg(Wo + k);
    out[g] = 1.f / (1.f + expf(-z));
}

// ---------------- launch ----------------
extern "C" void kernel_launch(void* const* d_in, const int* in_sizes, int n_in,
                              void* d_out, int out_size) {
    const float* feat      = (const float*)d_in[0];
    const int*   src       = (const int*)d_in[1];
    const int*   dst       = (const int*)d_in[2];
    const int*   graph_ids = (const int*)d_in[3];
    const float* W1        = (const float*)d_in[4];
    const float* b1        = (const float*)d_in[5];
    const float* W2        = (const float*)d_in[6];
    const float* b2        = (const float*)d_in[7];
    const float* Wo        = (const float*)d_in[8];
    const float* bo        = (const float*)d_in[9];
    float* out = (float*)d_out;

    const int T = 256;
    k_zero_all<<<(2000000 + T - 1) / T, T>>>();
    k_degrees<<<((N_EDGES / 4) + T - 1) / T, T>>>(src, dst);
    k_proj1<<<(N_NODES + T - 1) / T, T>>>(feat, W1);
    k_scatter1<<<(N_EDGES + T - 1) / T, T>>>(src, dst);
    k_h1_proj2<<<(N_NODES + T - 1) / T, T>>>(W2, b1);
    k_zero_agg2<<<(1000000 + T - 1) / T, T>>>();
    k_scatter2<<<(N_EDGES + T - 1) / T, T>>>(src, dst);
    k_graph_reduce<<<(N_NODES + T - 1) / T, T>>>(graph_ids, b2);
    k_final<<<(N_GRAPHS + T - 1) / T, T>>>(Wo, bo, out);
}